// round 1
// baseline (speedup 1.0000x reference)
#include <cuda_runtime.h>
#include <math.h>
#include <stdint.h>

#define NLV 16
#define TSZ (1u << 19)
#define TMASK (TSZ - 1u)

struct ResParams { int r[NLV]; };

__global__ void __launch_bounds__(256) hash_enc_kernel(
    const float* __restrict__ pos,
    const float* __restrict__ tables,
    float2* __restrict__ out,
    int npts, ResParams rp)
{
    int tid = blockIdx.x * 256 + threadIdx.x;
    int p = tid >> 4;
    if (p >= npts) return;
    int l = tid & 15;

    // 16 consecutive lanes read the same 3 floats -> L1 broadcast, 1 wavefront
    float px = __ldg(pos + 3 * (size_t)p + 0);
    float py = __ldg(pos + 3 * (size_t)p + 1);
    float pz = __ldg(pos + 3 * (size_t)p + 2);

    int res = rp.r[l];
    float fr = (float)(res - 1);
    float sx = px * fr, sy = py * fr, sz = pz * fr;
    float fx = floorf(sx), fy = floorf(sy), fz = floorf(sz);
    float wx = sx - fx, wy = sy - fy, wz = sz - fz;
    int ix = (int)fx, iy = (int)fy, iz = (int)fz;

    int rm = res - 1;
    int x0 = min(max(ix, 0), rm),     x1 = min(max(ix + 1, 0), rm);
    int y0 = min(max(iy, 0), rm),     y1 = min(max(iy + 1, 0), rm);
    int z0 = min(max(iz, 0), rm),     z1 = min(max(iz + 1, 0), rm);

    const unsigned P1 = 2654435761u, P2 = 805459861u, P3 = 3674653429u;
    unsigned hx0 = (unsigned)x0 * P1, hx1 = (unsigned)x1 * P1;
    unsigned hy0 = (unsigned)y0 * P2, hy1 = (unsigned)y1 * P2;
    unsigned hz0 = (unsigned)z0 * P3, hz1 = (unsigned)z1 * P3;

    const float2* __restrict__ tab =
        reinterpret_cast<const float2*>(tables) + (size_t)l * TSZ;

    // 8 independent gathers issued back-to-back for MLP
    float2 v000 = __ldg(tab + ((hx0 ^ hy0 ^ hz0) & TMASK));
    float2 v001 = __ldg(tab + ((hx0 ^ hy0 ^ hz1) & TMASK));
    float2 v010 = __ldg(tab + ((hx0 ^ hy1 ^ hz0) & TMASK));
    float2 v011 = __ldg(tab + ((hx0 ^ hy1 ^ hz1) & TMASK));
    float2 v100 = __ldg(tab + ((hx1 ^ hy0 ^ hz0) & TMASK));
    float2 v101 = __ldg(tab + ((hx1 ^ hy0 ^ hz1) & TMASK));
    float2 v110 = __ldg(tab + ((hx1 ^ hy1 ^ hz0) & TMASK));
    float2 v111 = __ldg(tab + ((hx1 ^ hy1 ^ hz1) & TMASK));

    float ux = 1.0f - wx, uy = 1.0f - wy, uz = 1.0f - wz;
    float w000 = ux * uy * uz, w001 = ux * uy * wz;
    float w010 = ux * wy * uz, w011 = ux * wy * wz;
    float w100 = wx * uy * uz, w101 = wx * uy * wz;
    float w110 = wx * wy * uz, w111 = wx * wy * wz;

    float f0 = v000.x * w000;
    float f1 = v000.y * w000;
    f0 = fmaf(v001.x, w001, f0);  f1 = fmaf(v001.y, w001, f1);
    f0 = fmaf(v010.x, w010, f0);  f1 = fmaf(v010.y, w010, f1);
    f0 = fmaf(v011.x, w011, f0);  f1 = fmaf(v011.y, w011, f1);
    f0 = fmaf(v100.x, w100, f0);  f1 = fmaf(v100.y, w100, f1);
    f0 = fmaf(v101.x, w101, f0);  f1 = fmaf(v101.y, w101, f1);
    f0 = fmaf(v110.x, w110, f0);  f1 = fmaf(v110.y, w110, f1);
    f0 = fmaf(v111.x, w111, f0);  f1 = fmaf(v111.y, w111, f1);

    // streaming store: don't let the 256MB output stream evict L2-resident tables
    float2 r = make_float2(f0, f1);
    __stcs(out + (size_t)p * 16 + l, r);
}

extern "C" void kernel_launch(void* const* d_in, const int* in_sizes, int n_in,
                              void* d_out, int out_size)
{
    const float* pos    = (const float*)d_in[0];   // [N,3] f32
    const float* tables = (const float*)d_in[1];   // [16, 2^19, 2] f32
    int npts = in_sizes[0] / 3;

    // Mirror numpy's float64 computation exactly (incl. int() truncation):
    // b = exp((log(2048)-log(16))/15); res_l = min(int(16*b**l), 2048)
    ResParams rp;
    double b = exp((log(2048.0) - log(16.0)) / 15.0);
    for (int l = 0; l < NLV; ++l) {
        double r = 16.0 * pow(b, (double)l);
        int ri = (int)r;           // truncation, like python int()
        if (ri > 2048) ri = 2048;
        rp.r[l] = ri;
    }

    long total = (long)npts * 16;
    int threads = 256;
    int blocks = (int)((total + threads - 1) / threads);
    hash_enc_kernel<<<blocks, threads>>>(pos, tables, (float2*)d_out, npts, rp);
}

// round 3
// speedup vs baseline: 1.2197x; 1.2197x over previous
#include <cuda_runtime.h>
#include <math.h>
#include <stdint.h>

#define NLV 16
#define TSZ (1u << 19)
#define TMASK (TSZ - 1u)
#define P1 2654435761u
#define P2 805459861u
#define P3 3674653429u

// dense z-paired grids for mid levels (levels 2..6): ~2.18M cells + margin
#define DENSE_CAP 2600000
__device__ float4 g_dense[DENSE_CAP];

struct LvlParams {
    int res[NLV];
    int mode[NLV];   // 0 = smem kernel handles, 1 = dense global, 2 = hash
    int dofs[NLV];   // offset into g_dense (float4 units) for mode 1
};

// ---------------------------------------------------------------------------
// Staging: build dense z-paired grids for mode-1 levels.
// g_dense[dofs + (x*r + y)*r + z] = { f(x,y,z).xy , f(x,y,min(z+1,r-1)).xy }
// ---------------------------------------------------------------------------
__global__ void __launch_bounds__(256) stage_dense_kernel(
    const float2* __restrict__ tables, LvlParams lp, int total)
{
    int i = blockIdx.x * 256 + threadIdx.x;
    int stride = gridDim.x * 256;
    for (; i < total; i += stride) {
        int l = 0, r = 0, rel = 0;
        #pragma unroll
        for (int k = 0; k < NLV; ++k) {
            if (lp.mode[k] == 1) {
                int n = lp.res[k] * lp.res[k] * lp.res[k];
                if (i >= lp.dofs[k] && i < lp.dofs[k] + n) { l = k; r = lp.res[k]; rel = i - lp.dofs[k]; }
            }
        }
        int z = rel % r;
        int t = rel / r;
        int y = t % r;
        int x = t / r;
        int z1 = min(z + 1, r - 1);
        unsigned hxy = (unsigned)x * P1 ^ (unsigned)y * P2;
        const float2* tab = tables + (size_t)l * TSZ;
        float2 a = __ldg(tab + ((hxy ^ (unsigned)z  * P3) & TMASK));
        float2 b = __ldg(tab + ((hxy ^ (unsigned)z1 * P3) & TMASK));
        g_dense[i] = make_float4(a.x, a.y, b.x, b.y);
    }
}

// ---------------------------------------------------------------------------
// Coarse kernel: levels 0 and 1 served from dense SMEM grids.
// ---------------------------------------------------------------------------
__global__ void hash_enc_coarse_kernel(
    const float* __restrict__ pos,
    const float2* __restrict__ tables,
    float4* __restrict__ out4,   // row p = 8 float4; levels 0,1 = out4[p*8]
    int npts, int r0, int r1)
{
    extern __shared__ float2 sm[];   // [r0^3 + r1^3]
    int n0 = r0 * r0 * r0;
    int n1 = r1 * r1 * r1;
    int ntot = n0 + n1;

    for (int i = threadIdx.x; i < ntot; i += blockDim.x) {
        int l = (i < n0) ? 0 : 1;
        int rel = (i < n0) ? i : i - n0;
        int r = (i < n0) ? r0 : r1;
        int z = rel % r;
        int t = rel / r;
        int y = t % r;
        int x = t / r;
        unsigned h = ((unsigned)x * P1 ^ (unsigned)y * P2 ^ (unsigned)z * P3) & TMASK;
        sm[i] = __ldg(tables + (size_t)l * TSZ + h);
    }
    __syncthreads();

    int gsz = gridDim.x * blockDim.x;
    for (int p = blockIdx.x * blockDim.x + threadIdx.x; p < npts; p += gsz) {
        float px = __ldg(pos + 3 * (size_t)p + 0);
        float py = __ldg(pos + 3 * (size_t)p + 1);
        float pz = __ldg(pos + 3 * (size_t)p + 2);

        float4 result;
        float* resf = (float*)&result;
        #pragma unroll
        for (int l = 0; l < 2; ++l) {
            int r = l ? r1 : r0;
            const float2* g = l ? (sm + n0) : sm;
            float fr = (float)(r - 1);
            float sx = px * fr, sy = py * fr, sz = pz * fr;
            float fx = floorf(sx), fy = floorf(sy), fz = floorf(sz);
            float wx = sx - fx, wy = sy - fy, wz = sz - fz;
            int rm = r - 1;
            int x0 = min(max((int)fx, 0), rm), x1 = min(x0 + 1, rm);
            int y0 = min(max((int)fy, 0), rm), y1 = min(y0 + 1, rm);
            int z0 = min(max((int)fz, 0), rm), z1 = min(z0 + 1, rm);

            int bx0 = x0 * r, bx1 = x1 * r;
            float2 v000 = g[(bx0 + y0) * r + z0];
            float2 v001 = g[(bx0 + y0) * r + z1];
            float2 v010 = g[(bx0 + y1) * r + z0];
            float2 v011 = g[(bx0 + y1) * r + z1];
            float2 v100 = g[(bx1 + y0) * r + z0];
            float2 v101 = g[(bx1 + y0) * r + z1];
            float2 v110 = g[(bx1 + y1) * r + z0];
            float2 v111 = g[(bx1 + y1) * r + z1];

            float ux = 1.0f - wx, uy = 1.0f - wy, uz = 1.0f - wz;
            float w000 = ux*uy*uz, w001 = ux*uy*wz, w010 = ux*wy*uz, w011 = ux*wy*wz;
            float w100 = wx*uy*uz, w101 = wx*uy*wz, w110 = wx*wy*uz, w111 = wx*wy*wz;

            float f0 = v000.x * w000, f1 = v000.y * w000;
            f0 = fmaf(v001.x, w001, f0);  f1 = fmaf(v001.y, w001, f1);
            f0 = fmaf(v010.x, w010, f0);  f1 = fmaf(v010.y, w010, f1);
            f0 = fmaf(v011.x, w011, f0);  f1 = fmaf(v011.y, w011, f1);
            f0 = fmaf(v100.x, w100, f0);  f1 = fmaf(v100.y, w100, f1);
            f0 = fmaf(v101.x, w101, f0);  f1 = fmaf(v101.y, w101, f1);
            f0 = fmaf(v110.x, w110, f0);  f1 = fmaf(v110.y, w110, f1);
            f0 = fmaf(v111.x, w111, f0);  f1 = fmaf(v111.y, w111, f1);
            resf[2 * l + 0] = f0;
            resf[2 * l + 1] = f1;
        }
        // FIX: row stride is 8 float4 (32 floats), not 4
        __stcs(out4 + (size_t)p * 8, result);
    }
}

// ---------------------------------------------------------------------------
// Main kernel: levels 2..6 via dense float4 grids (4 gathers),
// levels 7..15 via hash tables (8 gathers). Levels 0,1 skipped.
// ---------------------------------------------------------------------------
__global__ void __launch_bounds__(256) hash_enc_main_kernel(
    const float* __restrict__ pos,
    const float2* __restrict__ tables,
    float2* __restrict__ out,
    int npts, LvlParams lp)
{
    int tid = blockIdx.x * 256 + threadIdx.x;
    int p = tid >> 4;
    if (p >= npts) return;
    int l = tid & 15;
    if (l < 2) return;   // handled by coarse kernel

    float px = __ldg(pos + 3 * (size_t)p + 0);
    float py = __ldg(pos + 3 * (size_t)p + 1);
    float pz = __ldg(pos + 3 * (size_t)p + 2);

    int res = lp.res[l];
    int rm = res - 1;
    float fr = (float)rm;
    float sx = px * fr, sy = py * fr, sz = pz * fr;
    float fx = floorf(sx), fy = floorf(sy), fz = floorf(sz);
    float wx = sx - fx, wy = sy - fy, wz = sz - fz;
    int x0 = min(max((int)fx, 0), rm), x1 = min(x0 + 1, rm);
    int y0 = min(max((int)fy, 0), rm), y1 = min(y0 + 1, rm);
    int z0 = min(max((int)fz, 0), rm), z1 = min(z0 + 1, rm);

    float ux = 1.0f - wx, uy = 1.0f - wy, uz = 1.0f - wz;
    float f0, f1;

    if (lp.mode[l] == 1) {
        // dense z-paired grid: 4 float4 gathers
        const float4* g = g_dense + lp.dofs[l];
        int bx0 = x0 * res, bx1 = x1 * res;
        float4 a00 = __ldg(g + (bx0 + y0) * res + z0);
        float4 a01 = __ldg(g + (bx0 + y1) * res + z0);
        float4 a10 = __ldg(g + (bx1 + y0) * res + z0);
        float4 a11 = __ldg(g + (bx1 + y1) * res + z0);

        float w00 = ux * uy, w01 = ux * wy, w10 = wx * uy, w11 = wx * wy;
        float w00z0 = w00 * uz, w00z1 = w00 * wz;
        float w01z0 = w01 * uz, w01z1 = w01 * wz;
        float w10z0 = w10 * uz, w10z1 = w10 * wz;
        float w11z0 = w11 * uz, w11z1 = w11 * wz;

        f0 = a00.x * w00z0;            f1 = a00.y * w00z0;
        f0 = fmaf(a00.z, w00z1, f0);   f1 = fmaf(a00.w, w00z1, f1);
        f0 = fmaf(a01.x, w01z0, f0);   f1 = fmaf(a01.y, w01z0, f1);
        f0 = fmaf(a01.z, w01z1, f0);   f1 = fmaf(a01.w, w01z1, f1);
        f0 = fmaf(a10.x, w10z0, f0);   f1 = fmaf(a10.y, w10z0, f1);
        f0 = fmaf(a10.z, w10z1, f0);   f1 = fmaf(a10.w, w10z1, f1);
        f0 = fmaf(a11.x, w11z0, f0);   f1 = fmaf(a11.y, w11z0, f1);
        f0 = fmaf(a11.z, w11z1, f0);   f1 = fmaf(a11.w, w11z1, f1);
    } else {
        unsigned hx0 = (unsigned)x0 * P1, hx1 = (unsigned)x1 * P1;
        unsigned hy0 = (unsigned)y0 * P2, hy1 = (unsigned)y1 * P2;
        unsigned hz0 = (unsigned)z0 * P3, hz1 = (unsigned)z1 * P3;
        const float2* tab = tables + (size_t)l * TSZ;
        float2 v000 = __ldg(tab + ((hx0 ^ hy0 ^ hz0) & TMASK));
        float2 v001 = __ldg(tab + ((hx0 ^ hy0 ^ hz1) & TMASK));
        float2 v010 = __ldg(tab + ((hx0 ^ hy1 ^ hz0) & TMASK));
        float2 v011 = __ldg(tab + ((hx0 ^ hy1 ^ hz1) & TMASK));
        float2 v100 = __ldg(tab + ((hx1 ^ hy0 ^ hz0) & TMASK));
        float2 v101 = __ldg(tab + ((hx1 ^ hy0 ^ hz1) & TMASK));
        float2 v110 = __ldg(tab + ((hx1 ^ hy1 ^ hz0) & TMASK));
        float2 v111 = __ldg(tab + ((hx1 ^ hy1 ^ hz1) & TMASK));

        float w000 = ux*uy*uz, w001 = ux*uy*wz, w010 = ux*wy*uz, w011 = ux*wy*wz;
        float w100 = wx*uy*uz, w101 = wx*uy*wz, w110 = wx*wy*uz, w111 = wx*wy*wz;

        f0 = v000.x * w000;            f1 = v000.y * w000;
        f0 = fmaf(v001.x, w001, f0);   f1 = fmaf(v001.y, w001, f1);
        f0 = fmaf(v010.x, w010, f0);   f1 = fmaf(v010.y, w010, f1);
        f0 = fmaf(v011.x, w011, f0);   f1 = fmaf(v011.y, w011, f1);
        f0 = fmaf(v100.x, w100, f0);   f1 = fmaf(v100.y, w100, f1);
        f0 = fmaf(v101.x, w101, f0);   f1 = fmaf(v101.y, w101, f1);
        f0 = fmaf(v110.x, w110, f0);   f1 = fmaf(v110.y, w110, f1);
        f0 = fmaf(v111.x, w111, f0);   f1 = fmaf(v111.y, w111, f1);
    }

    __stcs(out + (size_t)p * 16 + l, make_float2(f0, f1));
}

// ---------------------------------------------------------------------------
extern "C" void kernel_launch(void* const* d_in, const int* in_sizes, int n_in,
                              void* d_out, int out_size)
{
    const float*  pos    = (const float*)d_in[0];
    const float2* tables = (const float2*)d_in[1];
    int npts = in_sizes[0] / 3;

    LvlParams lp;
    double b = exp((log(2048.0) - log(16.0)) / 15.0);
    for (int l = 0; l < NLV; ++l) {
        double r = 16.0 * pow(b, (double)l);
        int ri = (int)r;
        if (ri > 2048) ri = 2048;
        lp.res[l] = ri;
    }

    int dtot = 0;
    for (int l = 0; l < NLV; ++l) {
        lp.mode[l] = 2;
        lp.dofs[l] = 0;
        if (l < 2) { lp.mode[l] = 0; continue; }
        if (l <= 6) {
            long n = (long)lp.res[l] * lp.res[l] * lp.res[l];
            if (dtot + n <= DENSE_CAP) {
                lp.mode[l] = 1;
                lp.dofs[l] = dtot;
                dtot += (int)n;
            }
        }
    }

    if (dtot > 0) {
        int blocks = (dtot + 255) / 256;
        stage_dense_kernel<<<blocks, 256>>>(tables, lp, dtot);
    }

    {
        int r0 = lp.res[0], r1 = lp.res[1];
        int smem = (r0 * r0 * r0 + r1 * r1 * r1) * (int)sizeof(float2);  // ~115KB
        cudaFuncSetAttribute(hash_enc_coarse_kernel,
                             cudaFuncAttributeMaxDynamicSharedMemorySize, smem);
        hash_enc_coarse_kernel<<<148, 1024, smem>>>(pos, tables, (float4*)d_out,
                                                    npts, r0, r1);
    }

    {
        long total = (long)npts * 16;
        int blocks = (int)((total + 255) / 256);
        hash_enc_main_kernel<<<blocks, 256>>>(pos, tables, (float2*)d_out, npts, lp);
    }
}

// round 5
// speedup vs baseline: 1.4046x; 1.1516x over previous
#include <cuda_runtime.h>
#include <cuda_fp16.h>
#include <math.h>
#include <stdint.h>

#define NLV 16
#define TSZ (1u << 19)
#define TMASK (TSZ - 1u)
#define P1 2654435761u
#define P2 805459861u
#define P3 3674653429u

// Dense yz-quad grids for levels 0..6: each 16B cell holds the 2x2 (y,z) corner
// quad as fp16x2 pairs, scaled by 256. ~2.19M cells = 35MB (L2-resident).
#define DENSE_CAP 2300000
#define FSCALE 256.0f
#define INV_FSCALE (1.0f / 256.0f)
__device__ uint4 g_dense[DENSE_CAP];

struct LvlParams {
    int res[NLV];
    int dofs[NLV];   // cumulative cell offset for dense levels
    int ndense;      // levels [0, ndense) are dense
};

__device__ __forceinline__ unsigned h2_to_u32(half2 h) {
    return *reinterpret_cast<unsigned*>(&h);
}
__device__ __forceinline__ float2 u32_to_f2(unsigned u) {
    half2 h = *reinterpret_cast<half2*>(&u);
    return __half22float2(h);
}

// ---------------------------------------------------------------------------
// Staging: build fp16 yz-quad dense grids.
// cell(l,x,y,z) = half2x4 { f(y,z), f(y,z1), f(y1,z), f(y1,z1) } * 256
// ---------------------------------------------------------------------------
__global__ void __launch_bounds__(256) stage_dense_kernel(
    const float2* __restrict__ tables, LvlParams lp, int total)
{
    int i = blockIdx.x * 256 + threadIdx.x;
    int stride = gridDim.x * 256;
    for (; i < total; i += stride) {
        int l = 0;
        #pragma unroll
        for (int k = 1; k < 8; ++k)
            if (k < lp.ndense && i >= lp.dofs[k]) l = k;
        int r = lp.res[l];
        int rel = i - lp.dofs[l];
        int z = rel % r;
        int t = rel / r;
        int y = t % r;
        int x = t / r;
        int rm = r - 1;
        int y1 = min(y + 1, rm);
        int z1 = min(z + 1, rm);

        unsigned hx  = (unsigned)x  * P1;
        unsigned hy0 = (unsigned)y  * P2, hy1 = (unsigned)y1 * P2;
        unsigned hz0 = (unsigned)z  * P3, hz1 = (unsigned)z1 * P3;
        const float2* tab = tables + (size_t)l * TSZ;
        float2 a = __ldg(tab + ((hx ^ hy0 ^ hz0) & TMASK));
        float2 b = __ldg(tab + ((hx ^ hy0 ^ hz1) & TMASK));
        float2 c = __ldg(tab + ((hx ^ hy1 ^ hz0) & TMASK));
        float2 d = __ldg(tab + ((hx ^ hy1 ^ hz1) & TMASK));

        uint4 q;
        q.x = h2_to_u32(__floats2half2_rn(a.x * FSCALE, a.y * FSCALE));  // (y0,z0)
        q.y = h2_to_u32(__floats2half2_rn(b.x * FSCALE, b.y * FSCALE));  // (y0,z1)
        q.z = h2_to_u32(__floats2half2_rn(c.x * FSCALE, c.y * FSCALE));  // (y1,z0)
        q.w = h2_to_u32(__floats2half2_rn(d.x * FSCALE, d.y * FSCALE));  // (y1,z1)
        g_dense[i] = q;
    }
}

// ---------------------------------------------------------------------------
// Main kernel: thread = (point, level).
// Levels < ndense: 2 uint4 gathers (x0, x1 corners; each holds yz quad).
// Levels >= ndense: 8 hashed float2 gathers.
// ---------------------------------------------------------------------------
__global__ void __launch_bounds__(256) hash_enc_main_kernel(
    const float* __restrict__ pos,
    const float2* __restrict__ tables,
    float2* __restrict__ out,
    int npts, LvlParams lp)
{
    int tid = blockIdx.x * 256 + threadIdx.x;
    int p = tid >> 4;
    if (p >= npts) return;
    int l = tid & 15;

    float px = __ldg(pos + 3 * (size_t)p + 0);
    float py = __ldg(pos + 3 * (size_t)p + 1);
    float pz = __ldg(pos + 3 * (size_t)p + 2);

    int res = lp.res[l];
    int rm = res - 1;
    float fr = (float)rm;
    float sx = px * fr, sy = py * fr, sz = pz * fr;
    float fx = floorf(sx), fy = floorf(sy), fz = floorf(sz);
    float wx = sx - fx, wy = sy - fy, wz = sz - fz;
    int x0 = min(max((int)fx, 0), rm), x1 = min(x0 + 1, rm);
    int y0 = min(max((int)fy, 0), rm);
    int z0 = min(max((int)fz, 0), rm);

    float ux = 1.0f - wx, uy = 1.0f - wy, uz = 1.0f - wz;
    float f0, f1;

    if (l < lp.ndense) {
        // dense yz-quad: 2 uint4 gathers (x0 and x1 corners)
        const uint4* g = g_dense + lp.dofs[l];
        int base0 = (x0 * res + y0) * res + z0;
        int base1 = (x1 * res + y0) * res + z0;
        uint4 q0 = __ldg(g + base0);
        uint4 q1 = __ldg(g + base1);

        float2 v000 = u32_to_f2(q0.x), v001 = u32_to_f2(q0.y);
        float2 v010 = u32_to_f2(q0.z), v011 = u32_to_f2(q0.w);
        float2 v100 = u32_to_f2(q1.x), v101 = u32_to_f2(q1.y);
        float2 v110 = u32_to_f2(q1.z), v111 = u32_to_f2(q1.w);

        // fold the 1/256 un-scale into the x-weights
        float uxs = ux * INV_FSCALE, wxs = wx * INV_FSCALE;
        float w000 = uxs*uy*uz, w001 = uxs*uy*wz, w010 = uxs*wy*uz, w011 = uxs*wy*wz;
        float w100 = wxs*uy*uz, w101 = wxs*uy*wz, w110 = wxs*wy*uz, w111 = wxs*wy*wz;

        f0 = v000.x * w000;            f1 = v000.y * w000;
        f0 = fmaf(v001.x, w001, f0);   f1 = fmaf(v001.y, w001, f1);
        f0 = fmaf(v010.x, w010, f0);   f1 = fmaf(v010.y, w010, f1);
        f0 = fmaf(v011.x, w011, f0);   f1 = fmaf(v011.y, w011, f1);
        f0 = fmaf(v100.x, w100, f0);   f1 = fmaf(v100.y, w100, f1);
        f0 = fmaf(v101.x, w101, f0);   f1 = fmaf(v101.y, w101, f1);
        f0 = fmaf(v110.x, w110, f0);   f1 = fmaf(v110.y, w110, f1);
        f0 = fmaf(v111.x, w111, f0);   f1 = fmaf(v111.y, w111, f1);
    } else {
        int y1 = min(y0 + 1, rm), z1 = min(z0 + 1, rm);
        unsigned hx0 = (unsigned)x0 * P1, hx1 = (unsigned)x1 * P1;
        unsigned hy0 = (unsigned)y0 * P2, hy1 = (unsigned)y1 * P2;
        unsigned hz0 = (unsigned)z0 * P3, hz1 = (unsigned)z1 * P3;
        const float2* tab = tables + (size_t)l * TSZ;
        float2 v000 = __ldg(tab + ((hx0 ^ hy0 ^ hz0) & TMASK));
        float2 v001 = __ldg(tab + ((hx0 ^ hy0 ^ hz1) & TMASK));
        float2 v010 = __ldg(tab + ((hx0 ^ hy1 ^ hz0) & TMASK));
        float2 v011 = __ldg(tab + ((hx0 ^ hy1 ^ hz1) & TMASK));
        float2 v100 = __ldg(tab + ((hx1 ^ hy0 ^ hz0) & TMASK));
        float2 v101 = __ldg(tab + ((hx1 ^ hy0 ^ hz1) & TMASK));
        float2 v110 = __ldg(tab + ((hx1 ^ hy1 ^ hz0) & TMASK));
        float2 v111 = __ldg(tab + ((hx1 ^ hy1 ^ hz1) & TMASK));

        float w000 = ux*uy*uz, w001 = ux*uy*wz, w010 = ux*wy*uz, w011 = ux*wy*wz;
        float w100 = wx*uy*uz, w101 = wx*uy*wz, w110 = wx*wy*uz, w111 = wx*wy*wz;

        f0 = v000.x * w000;            f1 = v000.y * w000;
        f0 = fmaf(v001.x, w001, f0);   f1 = fmaf(v001.y, w001, f1);
        f0 = fmaf(v010.x, w010, f0);   f1 = fmaf(v010.y, w010, f1);
        f0 = fmaf(v011.x, w011, f0);   f1 = fmaf(v011.y, w011, f1);
        f0 = fmaf(v100.x, w100, f0);   f1 = fmaf(v100.y, w100, f1);
        f0 = fmaf(v101.x, w101, f0);   f1 = fmaf(v101.y, w101, f1);
        f0 = fmaf(v110.x, w110, f0);   f1 = fmaf(v110.y, w110, f1);
        f0 = fmaf(v111.x, w111, f0);   f1 = fmaf(v111.y, w111, f1);
    }

    __stcs(out + (size_t)p * 16 + l, make_float2(f0, f1));
}

// ---------------------------------------------------------------------------
extern "C" void kernel_launch(void* const* d_in, const int* in_sizes, int n_in,
                              void* d_out, int out_size)
{
    const float*  pos    = (const float*)d_in[0];
    const float2* tables = (const float2*)d_in[1];
    int npts = in_sizes[0] / 3;

    LvlParams lp;
    double b = exp((log(2048.0) - log(16.0)) / 15.0);
    for (int l = 0; l < NLV; ++l) {
        double r = 16.0 * pow(b, (double)l);
        int ri = (int)r;
        if (ri > 2048) ri = 2048;
        lp.res[l] = ri;
    }

    // densify levels greedily while they fit the static scratch
    int dtot = 0;
    lp.ndense = 0;
    for (int l = 0; l < NLV; ++l) lp.dofs[l] = 0;
    for (int l = 0; l < NLV; ++l) {
        long n = (long)lp.res[l] * lp.res[l] * lp.res[l];
        if (dtot + n > DENSE_CAP) break;
        lp.dofs[l] = dtot;
        dtot += (int)n;
        lp.ndense = l + 1;
    }

    if (dtot > 0) {
        int blocks = (dtot + 255) / 256;
        if (blocks > 8880) blocks = 8880;   // grid-stride
        stage_dense_kernel<<<blocks, 256>>>(tables, lp, dtot);
    }

    long total = (long)npts * 16;
    int blocks = (int)((total + 255) / 256);
    hash_enc_main_kernel<<<blocks, 256>>>(pos, tables, (float2*)d_out, npts, lp);
}

// round 6
// speedup vs baseline: 1.4341x; 1.0210x over previous
#include <cuda_runtime.h>
#include <cuda_fp16.h>
#include <math.h>

#define NLV 16
#define NDENSE 8
#define NHASH 8
#define TSZ (1u << 19)
#define TMASK (TSZ - 1u)
#define P1 2654435761u
#define P2 805459861u
#define P3 3674653429u
#define FSCALE 256.0f
#define INV_FSCALE (1.0f / 256.0f)

// Dense yz-quad grids, x-fastest, fp16x4 per 16B cell. Levels 0..7: ~5.85M cells.
#define DENSE_CAP 6000000
__device__ uint4 g_dense[DENSE_CAP];           // 96 MB
__device__ unsigned g_htab[NHASH << 19];       // fp16x2 copies of tables 8..15 (16 MB)

struct LvlParams {
    int res[NLV];
    int dofs[NDENSE];    // cell offset per dense level
    int soff[NDENSE];    // staging thread offset per dense level
};

__device__ __forceinline__ unsigned h2u(half2 h) { return *reinterpret_cast<unsigned*>(&h); }
__device__ __forceinline__ float2 u2f(unsigned u) {
    half2 h = *reinterpret_cast<half2*>(&u);
    return __half22float2(h);
}

// ---------------------------------------------------------------------------
// fp16 copies of hashed tables (levels 8..15), coalesced.
// ---------------------------------------------------------------------------
__global__ void __launch_bounds__(256) stage_htab_kernel(const float2* __restrict__ tables)
{
    int i = blockIdx.x * 256 + threadIdx.x;
    if (i >= (NHASH << 19)) return;
    float2 v = __ldg(tables + ((size_t)8 << 19) + i);
    g_htab[i] = h2u(__floats2half2_rn(v.x * FSCALE, v.y * FSCALE));
}

// ---------------------------------------------------------------------------
// Dense staging: thread = (level, x, 2x2 yz cell block). 9 vertex gathers -> 4 cells.
// Cell layout: idx = dofs[l] + (y*r + z)*r + x  (x fastest for lane-pair coalescing)
// Cell quad: q.x=(y0,z0) q.y=(y0,z1) q.z=(y1,z0) q.w=(y1,z1)
// ---------------------------------------------------------------------------
__global__ void __launch_bounds__(256) stage_dense_kernel(
    const float2* __restrict__ tables, LvlParams lp, int total)
{
    int i = blockIdx.x * 256 + threadIdx.x;
    if (i >= total) return;

    int l = 0;
    #pragma unroll
    for (int k = 1; k < NDENSE; ++k)
        if (i >= lp.soff[k]) l = k;
    int r = lp.res[l];
    int rm = r - 1;
    int nz2 = (r + 1) >> 1;
    int rel = i - lp.soff[l];
    int x = rel % r;
    int t = rel / r;
    int zb = t % nz2;
    int yb = t / nz2;
    int y0 = yb * 2, z0 = zb * 2;

    unsigned hx = (unsigned)x * P1;
    const float2* tab = tables + (size_t)l * TSZ;

    unsigned vq[3][3];
    #pragma unroll
    for (int a = 0; a < 3; ++a) {
        int yv = min(y0 + a, rm);
        unsigned hy = (unsigned)yv * P2;
        #pragma unroll
        for (int c = 0; c < 3; ++c) {
            int zv = min(z0 + c, rm);
            float2 v = __ldg(tab + ((hx ^ hy ^ ((unsigned)zv * P3)) & TMASK));
            vq[a][c] = h2u(__floats2half2_rn(v.x * FSCALE, v.y * FSCALE));
        }
    }

    #pragma unroll
    for (int a = 0; a < 2; ++a) {
        int y = y0 + a;
        if (y >= r) break;
        #pragma unroll
        for (int c = 0; c < 2; ++c) {
            int z = z0 + c;
            if (z >= r) continue;
            uint4 q;
            q.x = vq[a][c];
            q.y = vq[a][c + 1];
            q.z = vq[a + 1][c];
            q.w = vq[a + 1][c + 1];
            g_dense[lp.dofs[l] + (y * r + z) * r + x] = q;
        }
    }
}

// ---------------------------------------------------------------------------
// Main kernel. 16 lanes per point. hl = lane&15, pair k = hl>>1, sub = hl&1.
// Phase A: dense level k   -- lane pair loads adjacent x-cells (1 line ~7/8).
// Phase B: hashed level 8+k -- lane sub handles its x-face (4 gathers).
// Pair partial sums combined via shfl_xor(1). sub=0 stores level k,
// sub=1 stores level 8+k.
// ---------------------------------------------------------------------------
__global__ void __launch_bounds__(256) hash_enc_main_kernel(
    const float* __restrict__ pos,
    float2* __restrict__ out,
    int npts, LvlParams lp)
{
    int tid = blockIdx.x * 256 + threadIdx.x;
    int p = tid >> 4;
    if (p >= npts) return;
    int hl = tid & 15;
    int k = hl >> 1;
    int sub = hl & 1;

    float px = __ldg(pos + 3 * (size_t)p + 0);
    float py = __ldg(pos + 3 * (size_t)p + 1);
    float pz = __ldg(pos + 3 * (size_t)p + 2);

    // ---------- phase A addresses (dense level k) ----------
    int rA = lp.res[k];
    int rmA = rA - 1;
    float frA = (float)rmA;
    float sxA = px * frA, syA = py * frA, szA = pz * frA;
    float fxA = floorf(sxA), fyA = floorf(syA), fzA = floorf(szA);
    float wxA = sxA - fxA, wyA = syA - fyA, wzA = szA - fzA;
    int x0A = min(max((int)fxA, 0), rmA);
    int y0A = min(max((int)fyA, 0), rmA);
    int z0A = min(max((int)fzA, 0), rmA);
    int xsA = min(x0A + sub, rmA);
    const uint4* gA = g_dense + lp.dofs[k];
    uint4 q = __ldg(gA + ((y0A * rA + z0A) * rA + xsA));

    // ---------- phase B addresses (hashed level 8+k) ----------
    int lB = 8 + k;
    int rB = lp.res[lB];
    int rmB = rB - 1;
    float frB = (float)rmB;
    float sxB = px * frB, syB = py * frB, szB = pz * frB;
    float fxB = floorf(sxB), fyB = floorf(syB), fzB = floorf(szB);
    float wxB = sxB - fxB, wyB = syB - fyB, wzB = szB - fzB;
    int x0B = min(max((int)fxB, 0), rmB);
    int y0B = min(max((int)fyB, 0), rmB);
    int z0B = min(max((int)fzB, 0), rmB);
    int xsB = min(x0B + sub, rmB);
    unsigned hxB = (unsigned)xsB * P1;
    unsigned hy0 = (unsigned)y0B * P2, hy1 = (unsigned)min(y0B + 1, rmB) * P2;
    unsigned hz0 = (unsigned)z0B * P3, hz1 = (unsigned)min(z0B + 1, rmB) * P3;
    const unsigned* ht = g_htab + ((size_t)k << 19);
    unsigned c00u = __ldg(ht + ((hxB ^ hy0 ^ hz0) & TMASK));
    unsigned c01u = __ldg(ht + ((hxB ^ hy0 ^ hz1) & TMASK));
    unsigned c10u = __ldg(ht + ((hxB ^ hy1 ^ hz0) & TMASK));
    unsigned c11u = __ldg(ht + ((hxB ^ hy1 ^ hz1) & TMASK));

    // ---------- phase A math ----------
    float2 a00 = u2f(q.x), a01 = u2f(q.y), a10 = u2f(q.z), a11 = u2f(q.w);
    float wxfA = (sub ? wxA : 1.0f - wxA) * INV_FSCALE;
    float uyA = 1.0f - wyA, uzA = 1.0f - wzA;
    float wA00 = wxfA * uyA * uzA, wA01 = wxfA * uyA * wzA;
    float wA10 = wxfA * wyA * uzA, wA11 = wxfA * wyA * wzA;
    float fA0 = a00.x * wA00, fA1 = a00.y * wA00;
    fA0 = fmaf(a01.x, wA01, fA0);  fA1 = fmaf(a01.y, wA01, fA1);
    fA0 = fmaf(a10.x, wA10, fA0);  fA1 = fmaf(a10.y, wA10, fA1);
    fA0 = fmaf(a11.x, wA11, fA0);  fA1 = fmaf(a11.y, wA11, fA1);
    fA0 += __shfl_xor_sync(0xFFFFFFFFu, fA0, 1);
    fA1 += __shfl_xor_sync(0xFFFFFFFFu, fA1, 1);

    // ---------- phase B math ----------
    float2 c00 = u2f(c00u), c01 = u2f(c01u), c10 = u2f(c10u), c11 = u2f(c11u);
    float wxfB = (sub ? wxB : 1.0f - wxB) * INV_FSCALE;
    float uyB = 1.0f - wyB, uzB = 1.0f - wzB;
    float wB00 = wxfB * uyB * uzB, wB01 = wxfB * uyB * wzB;
    float wB10 = wxfB * wyB * uzB, wB11 = wxfB * wyB * wzB;
    float fB0 = c00.x * wB00, fB1 = c00.y * wB00;
    fB0 = fmaf(c01.x, wB01, fB0);  fB1 = fmaf(c01.y, wB01, fB1);
    fB0 = fmaf(c10.x, wB10, fB0);  fB1 = fmaf(c10.y, wB10, fB1);
    fB0 = fmaf(c11.x, wB11, fB0);  fB1 = fmaf(c11.y, wB11, fB1);
    fB0 += __shfl_xor_sync(0xFFFFFFFFu, fB0, 1);
    fB1 += __shfl_xor_sync(0xFFFFFFFFu, fB1, 1);

    // ---------- store ----------
    int lvl = sub ? lB : k;
    float2 v;
    v.x = sub ? fB0 : fA0;
    v.y = sub ? fB1 : fA1;
    __stcs(out + (size_t)p * 16 + lvl, v);
}

// ---------------------------------------------------------------------------
extern "C" void kernel_launch(void* const* d_in, const int* in_sizes, int n_in,
                              void* d_out, int out_size)
{
    const float*  pos    = (const float*)d_in[0];
    const float2* tables = (const float2*)d_in[1];
    int npts = in_sizes[0] / 3;

    LvlParams lp;
    double b = exp((log(2048.0) - log(16.0)) / 15.0);
    for (int l = 0; l < NLV; ++l) {
        double r = 16.0 * pow(b, (double)l);
        int ri = (int)r;
        if (ri > 2048) ri = 2048;
        lp.res[l] = ri;
    }

    // dense level cell offsets + staging thread offsets
    int dtot = 0, stot = 0;
    for (int l = 0; l < NDENSE; ++l) {
        int r = lp.res[l];
        lp.dofs[l] = dtot;
        lp.soff[l] = stot;
        dtot += r * r * r;
        int n2 = (r + 1) / 2;
        stot += r * n2 * n2;
    }
    // dtot <= DENSE_CAP by construction (~5.85M)

    stage_htab_kernel<<<((NHASH << 19) + 255) / 256, 256>>>(tables);
    stage_dense_kernel<<<(stot + 255) / 256, 256>>>(tables, lp, stot);

    long total = (long)npts * 16;
    int blocks = (int)((total + 255) / 256);
    hash_enc_main_kernel<<<blocks, 256>>>(pos, (float2*)d_out, npts, lp);
}